// round 2
// baseline (speedup 1.0000x reference)
#include <cuda_runtime.h>

#define BB 4
#define HH 16
#define DD 4
#define HID 256
#define NN 1024
#define LOG2E 1.4426950408889634f
#define QPRE (0.5f * LOG2E)   /* SCALE * log2(e), folded into q at projection time */

// ---------------- device scratch (no allocation allowed) ----------------
__device__ float g_qh[BB*HH*NN*DD];   // [b][h][n][d], pre-scaled by QPRE
__device__ float g_kd[BB*HH*DD*NN];   // [b][h][d][n]
__device__ float g_vd[BB*HH*DD*NN];   // [b][h][d][n]
__device__ float g_x2[BB*HH*DD*NN];   // [b][h*4+d][n]  (post-transpose layout)

__device__ __forceinline__ float ex2f(float x){
    float y; asm("ex2.approx.ftz.f32 %0, %1;" : "=f"(y) : "f"(x)); return y;
}
__device__ __forceinline__ float wred(float v){
    v += __shfl_xor_sync(0xffffffffu, v, 16);
    v += __shfl_xor_sync(0xffffffffu, v, 8);
    v += __shfl_xor_sync(0xffffffffu, v, 4);
    v += __shfl_xor_sync(0xffffffffu, v, 2);
    v += __shfl_xor_sync(0xffffffffu, v, 1);
    return v;
}

// ---------------- kernel 1: projections + head scatter ----------------
// grid (NN/128, BB, 3), block 256
// thread: nq = t&31 -> 4 n's (float4), og = t>>5 -> 8 output channels
__global__ void proj_kernel(const float* __restrict__ q,
                            const float* __restrict__ k,
                            const float* __restrict__ v,
                            const float* __restrict__ Wq,
                            const float* __restrict__ Wk,
                            const float* __restrict__ Wv)
{
    const int z  = blockIdx.z;
    const int b  = blockIdx.y;
    const int n0 = blockIdx.x * 128;

    const float* x = (z == 0) ? q : (z == 1) ? k : v;
    const float* W = (z == 0) ? Wq : (z == 1) ? Wk : Wv;

    const int t  = threadIdx.x;
    const int nq = t & 31;
    const int og = t >> 5;
    const int n  = n0 + nq * 4;

    float acc[8][4];
    #pragma unroll
    for (int i = 0; i < 8; i++)
        #pragma unroll
        for (int jj = 0; jj < 4; jj++) acc[i][jj] = 0.f;

    const float4* xp = (const float4*)(x + (size_t)b * HID * NN + n);
    const float*  Wp = W + og * 8 * HID;

    #pragma unroll 4
    for (int c = 0; c < HID; c++) {
        float4 xv = __ldg(xp + (size_t)c * (NN / 4));
        #pragma unroll
        for (int i = 0; i < 8; i++) {
            float w = __ldg(Wp + i * HID + c);
            acc[i][0] = fmaf(w, xv.x, acc[i][0]);
            acc[i][1] = fmaf(w, xv.y, acc[i][1]);
            acc[i][2] = fmaf(w, xv.z, acc[i][2]);
            acc[i][3] = fmaf(w, xv.w, acc[i][3]);
        }
    }

    // scatter into head layouts. Mapping derived from reshape(B,D,N,H):
    //   channel o, position n  ->  d = o>>4, a = o&15, b2 = n>>4, h = n&15, n2 = a*64+b2
    #pragma unroll
    for (int i = 0; i < 8; i++) {
        const int o = og * 8 + i;
        const int d = o >> 4, a = o & 15;
        #pragma unroll
        for (int jj = 0; jj < 4; jj++) {
            const int np = n + jj;
            const int b2 = np >> 4, h = np & 15;
            const int n2 = a * 64 + b2;
            const float val = acc[i][jj];
            if (z == 0)      g_qh[(((b * HH + h) * NN + n2) << 2) + d] = val * QPRE;
            else if (z == 1) g_kd[((b * HH + h) * DD + d) * NN + n2] = val;
            else             g_vd[((b * HH + h) * DD + d) * NN + n2] = val;
        }
    }
}

// ---------------- kernel 2: fused attention ----------------
// grid (16, 64): x = 64-row chunk, y = bh. block 256 (8 warps).
// Each warp processes 4 rows simultaneously (amortizes K/V smem reads 4x).
__global__ void __launch_bounds__(256) attn_kernel(const float* __restrict__ bias)
{
    __shared__ float sK[DD * NN];
    __shared__ float sV[DD * NN];

    const int bh    = blockIdx.y;
    const int chunk = blockIdx.x;
    const int t     = threadIdx.x;

    // load K,V head tiles (4096 floats each) into smem
    {
        const float4* gk = (const float4*)(g_kd + bh * DD * NN);
        const float4* gv = (const float4*)(g_vd + bh * DD * NN);
        float4* sk4 = (float4*)sK;
        float4* sv4 = (float4*)sV;
        #pragma unroll
        for (int i = 0; i < 4; i++) {
            sk4[t + i * 256] = gk[t + i * 256];
            sv4[t + i * 256] = gv[t + i * 256];
        }
    }
    __syncthreads();

    const int warp = t >> 5, lane = t & 31;
    const float4* sk4 = (const float4*)sK;
    const float4* sv4 = (const float4*)sV;
    const float*  biasbh = bias + (size_t)bh * NN * NN;

    #pragma unroll 1
    for (int pass = 0; pass < 2; pass++) {
        const int row0 = chunk * 64 + warp * 8 + pass * 4;

        float4 qr[4];
        const float4* bp[4];
        #pragma unroll
        for (int j = 0; j < 4; j++) {
            qr[j] = *(const float4*)(g_qh + (bh * NN + row0 + j) * 4);
            bp[j] = (const float4*)(biasbh + (size_t)(row0 + j) * NN);
        }

        float sum[4] = {0.f, 0.f, 0.f, 0.f};
        float acc[4][4];
        #pragma unroll
        for (int j = 0; j < 4; j++)
            #pragma unroll
            for (int d = 0; d < 4; d++) acc[j][d] = 0.f;

        #pragma unroll
        for (int i = 0; i < 8; i++) {
            const int mi = i * 32 + lane;           // float4 index into m
            const float4 k0 = sk4[mi];
            const float4 k1 = sk4[256 + mi];
            const float4 k2 = sk4[512 + mi];
            const float4 k3 = sk4[768 + mi];
            const float4 v0 = sv4[mi];
            const float4 v1 = sv4[256 + mi];
            const float4 v2 = sv4[512 + mi];
            const float4 v3 = sv4[768 + mi];

            #pragma unroll
            for (int j = 0; j < 4; j++) {
                const float4 bb = __ldg(&bp[j][mi]);
                // q pre-scaled by SCALE*log2e -> score*log2e = dot + bias*log2e
                float z0 = fmaf(qr[j].x, k0.x, fmaf(qr[j].y, k1.x, fmaf(qr[j].z, k2.x, qr[j].w * k3.x)));
                float z1 = fmaf(qr[j].x, k0.y, fmaf(qr[j].y, k1.y, fmaf(qr[j].z, k2.y, qr[j].w * k3.y)));
                float z2 = fmaf(qr[j].x, k0.z, fmaf(qr[j].y, k1.z, fmaf(qr[j].z, k2.z, qr[j].w * k3.z)));
                float z3 = fmaf(qr[j].x, k0.w, fmaf(qr[j].y, k1.w, fmaf(qr[j].z, k2.w, qr[j].w * k3.w)));
                const float e0 = ex2f(fmaf(bb.x, LOG2E, z0));
                const float e1 = ex2f(fmaf(bb.y, LOG2E, z1));
                const float e2 = ex2f(fmaf(bb.z, LOG2E, z2));
                const float e3 = ex2f(fmaf(bb.w, LOG2E, z3));
                sum[j] += (e0 + e1) + (e2 + e3);
                acc[j][0] = fmaf(e0, v0.x, fmaf(e1, v0.y, fmaf(e2, v0.z, fmaf(e3, v0.w, acc[j][0]))));
                acc[j][1] = fmaf(e0, v1.x, fmaf(e1, v1.y, fmaf(e2, v1.z, fmaf(e3, v1.w, acc[j][1]))));
                acc[j][2] = fmaf(e0, v2.x, fmaf(e1, v2.y, fmaf(e2, v2.z, fmaf(e3, v2.w, acc[j][2]))));
                acc[j][3] = fmaf(e0, v3.x, fmaf(e1, v3.y, fmaf(e2, v3.z, fmaf(e3, v3.w, acc[j][3]))));
            }
        }

        // warp reductions (all-lanes butterfly), lane 0 writes
        #pragma unroll
        for (int j = 0; j < 4; j++) {
            sum[j] = wred(sum[j]);
            #pragma unroll
            for (int d = 0; d < 4; d++) acc[j][d] = wred(acc[j][d]);
        }
        if (lane == 0) {
            float* ob = g_x2 + bh * 4 * NN;   // channel base = b*64 + h*4 = 4*bh
            #pragma unroll
            for (int j = 0; j < 4; j++) {
                const float inv = 1.0f / sum[j];
                #pragma unroll
                for (int d = 0; d < 4; d++)
                    ob[d * NN + row0 + j] = acc[j][d] * inv;
            }
        }
    }
}

// ---------------- kernel 3: output conv + BN(eval) + LeakyReLU ----------------
// grid (NN/64, BB), block 512. thread: nq = t&15 -> 4 n's, og = t>>4 -> 8 channels
__global__ void __launch_bounds__(512) out_kernel(
    const float* __restrict__ Wo, const float* __restrict__ bo,
    const float* __restrict__ gamma, const float* __restrict__ beta,
    const float* __restrict__ rmean, const float* __restrict__ rvar,
    float* __restrict__ out)
{
    const int b  = blockIdx.y;
    const int n0 = blockIdx.x * 64;
    const int t  = threadIdx.x;
    const int nq = t & 15;
    const int og = t >> 4;                // [0,32): 8 channels each
    const int n  = n0 + nq * 4;

    float acc[8][4];
    #pragma unroll
    for (int i = 0; i < 8; i++)
        #pragma unroll
        for (int jj = 0; jj < 4; jj++) acc[i][jj] = 0.f;

    const float4* xp = (const float4*)(g_x2 + b * 64 * NN + n);
    const float*  Wp = Wo + og * 8 * 64;

    #pragma unroll 4
    for (int c = 0; c < 64; c++) {
        float4 xv = xp[c * (NN / 4)];
        #pragma unroll
        for (int i = 0; i < 8; i++) {
            float w = __ldg(Wp + i * 64 + c);
            acc[i][0] = fmaf(w, xv.x, acc[i][0]);
            acc[i][1] = fmaf(w, xv.y, acc[i][1]);
            acc[i][2] = fmaf(w, xv.z, acc[i][2]);
            acc[i][3] = fmaf(w, xv.w, acc[i][3]);
        }
    }

    #pragma unroll
    for (int i = 0; i < 8; i++) {
        const int o = og * 8 + i;
        const float inv  = rsqrtf(__ldg(rvar + o) + 1e-5f);
        const float sc   = __ldg(gamma + o) * inv;
        const float sh   = __ldg(beta + o) - __ldg(rmean + o) * sc;
        const float bse  = fmaf(__ldg(bo + o), sc, sh);
        float4 r;
        r.x = fmaf(acc[i][0], sc, bse);
        r.y = fmaf(acc[i][1], sc, bse);
        r.z = fmaf(acc[i][2], sc, bse);
        r.w = fmaf(acc[i][3], sc, bse);
        r.x = r.x > 0.f ? r.x : 0.2f * r.x;
        r.y = r.y > 0.f ? r.y : 0.2f * r.y;
        r.z = r.z > 0.f ? r.z : 0.2f * r.z;
        r.w = r.w > 0.f ? r.w : 0.2f * r.w;
        *(float4*)(out + ((size_t)b * HID + o) * NN + n) = r;
    }
}

// ---------------- launch ----------------
extern "C" void kernel_launch(void* const* d_in, const int* in_sizes, int n_in,
                              void* d_out, int out_size)
{
    const float* q    = (const float*)d_in[0];
    const float* k    = (const float*)d_in[1];
    const float* v    = (const float*)d_in[2];
    const float* bias = (const float*)d_in[3];
    const float* Wq   = (const float*)d_in[4];
    const float* Wk   = (const float*)d_in[5];
    const float* Wv   = (const float*)d_in[6];
    const float* Wo   = (const float*)d_in[7];
    const float* bo   = (const float*)d_in[8];
    const float* gm   = (const float*)d_in[9];
    const float* bt   = (const float*)d_in[10];
    const float* rm   = (const float*)d_in[11];
    const float* rv   = (const float*)d_in[12];
    float* out = (float*)d_out;

    proj_kernel<<<dim3(NN / 128, BB, 3), 256>>>(q, k, v, Wq, Wk, Wv);
    attn_kernel<<<dim3(16, BB * HH), 256>>>(bias);
    out_kernel<<<dim3(NN / 64, BB), 512>>>(Wo, bo, gm, bt, rm, rv, out);
}

// round 4
// speedup vs baseline: 1.1634x; 1.1634x over previous
#include <cuda_runtime.h>

#define BB 4
#define HH 16
#define DD 4
#define HID 256
#define NN 1024
#define LOG2E 1.4426950408889634f
#define QPRE (0.5f * LOG2E)   /* SCALE * log2(e), folded into q at projection time */

// ---------------- device scratch (no allocation allowed) ----------------
__device__ float g_qh[BB*HH*NN*DD];   // [b][h][n][d], pre-scaled by QPRE
__device__ float g_kd[BB*HH*DD*NN];   // [b][h][d][n]
__device__ float g_vd[BB*HH*DD*NN];   // [b][h][d][n]
__device__ float g_x2[BB*HH*DD*NN];   // [b][h*4+d][n]  (post-transpose layout)

__device__ __forceinline__ float ex2f(float x){
    float y; asm("ex2.approx.ftz.f32 %0, %1;" : "=f"(y) : "f"(x)); return y;
}
__device__ __forceinline__ float wred(float v){
    v += __shfl_xor_sync(0xffffffffu, v, 16);
    v += __shfl_xor_sync(0xffffffffu, v, 8);
    v += __shfl_xor_sync(0xffffffffu, v, 4);
    v += __shfl_xor_sync(0xffffffffu, v, 2);
    v += __shfl_xor_sync(0xffffffffu, v, 1);
    return v;
}

// ---------------- kernel 1: projections + head scatter ----------------
// grid (NN/32, BB, 3), block 256
// thread: nq = t&7 -> 4 n's (float4) within a 32-n block, og = t>>3 -> 2 output channels
__global__ void __launch_bounds__(256) proj_kernel(
    const float* __restrict__ q,
    const float* __restrict__ k,
    const float* __restrict__ v,
    const float* __restrict__ Wq,
    const float* __restrict__ Wk,
    const float* __restrict__ Wv)
{
    const int z  = blockIdx.z;
    const int b  = blockIdx.y;
    const int n0 = blockIdx.x * 32;

    const float* x = (z == 0) ? q : (z == 1) ? k : v;
    const float* W = (z == 0) ? Wq : (z == 1) ? Wk : Wv;

    const int t  = threadIdx.x;
    const int nq = t & 7;
    const int og = t >> 3;               // [0,32): 2 channels each
    const int n  = n0 + nq * 4;

    float acc[2][4];
    #pragma unroll
    for (int i = 0; i < 2; i++)
        #pragma unroll
        for (int jj = 0; jj < 4; jj++) acc[i][jj] = 0.f;

    const float4* xp = (const float4*)(x + (size_t)b * HID * NN + n);
    const float*  Wp = W + og * 2 * HID;

    #pragma unroll 8
    for (int c = 0; c < HID; c++) {
        float4 xv = __ldg(xp + (size_t)c * (NN / 4));
        float w0 = __ldg(Wp + c);
        float w1 = __ldg(Wp + HID + c);
        acc[0][0] = fmaf(w0, xv.x, acc[0][0]);
        acc[0][1] = fmaf(w0, xv.y, acc[0][1]);
        acc[0][2] = fmaf(w0, xv.z, acc[0][2]);
        acc[0][3] = fmaf(w0, xv.w, acc[0][3]);
        acc[1][0] = fmaf(w1, xv.x, acc[1][0]);
        acc[1][1] = fmaf(w1, xv.y, acc[1][1]);
        acc[1][2] = fmaf(w1, xv.z, acc[1][2]);
        acc[1][3] = fmaf(w1, xv.w, acc[1][3]);
    }

    // scatter into head layouts. Mapping derived from reshape(B,D,N,H):
    //   channel o, position n  ->  d = o>>4, a = o&15, b2 = n>>4, h = n&15, n2 = a*64+b2
    #pragma unroll
    for (int i = 0; i < 2; i++) {
        const int o = og * 2 + i;
        const int d = o >> 4, a = o & 15;
        #pragma unroll
        for (int jj = 0; jj < 4; jj++) {
            const int np = n + jj;
            const int b2 = np >> 4, h = np & 15;
            const int n2 = a * 64 + b2;
            const float val = acc[i][jj];
            if (z == 0)      g_qh[(((b * HH + h) * NN + n2) << 2) + d] = val * QPRE;
            else if (z == 1) g_kd[((b * HH + h) * DD + d) * NN + n2] = val;
            else             g_vd[((b * HH + h) * DD + d) * NN + n2] = val;
        }
    }
}

// ---------------- kernel 2: fused attention ----------------
// grid (16, 64): x = 64-row chunk, y = bh. block 256 (8 warps).
// Each warp processes 4 rows simultaneously (amortizes K/V smem reads 4x).
__global__ void __launch_bounds__(256) attn_kernel(const float* __restrict__ bias)
{
    __shared__ float sK[DD * NN];
    __shared__ float sV[DD * NN];

    const int bh    = blockIdx.y;
    const int chunk = blockIdx.x;
    const int t     = threadIdx.x;

    // load K,V head tiles (4096 floats each) into smem
    {
        const float4* gk = (const float4*)(g_kd + bh * DD * NN);
        const float4* gv = (const float4*)(g_vd + bh * DD * NN);
        float4* sk4 = (float4*)sK;
        float4* sv4 = (float4*)sV;
        #pragma unroll
        for (int i = 0; i < 4; i++) {
            sk4[t + i * 256] = gk[t + i * 256];
            sv4[t + i * 256] = gv[t + i * 256];
        }
    }
    __syncthreads();

    const int warp = t >> 5, lane = t & 31;
    const float4* sk4 = (const float4*)sK;
    const float4* sv4 = (const float4*)sV;
    const float*  biasbh = bias + (size_t)bh * NN * NN;

    #pragma unroll 1
    for (int pass = 0; pass < 2; pass++) {
        const int row0 = chunk * 64 + warp * 8 + pass * 4;

        float4 qr[4];
        const float4* bp[4];
        #pragma unroll
        for (int j = 0; j < 4; j++) {
            qr[j] = *(const float4*)(g_qh + (bh * NN + row0 + j) * 4);
            bp[j] = (const float4*)(biasbh + (size_t)(row0 + j) * NN);
        }

        float sum[4] = {0.f, 0.f, 0.f, 0.f};
        float acc[4][4];
        #pragma unroll
        for (int j = 0; j < 4; j++)
            #pragma unroll
            for (int d = 0; d < 4; d++) acc[j][d] = 0.f;

        #pragma unroll
        for (int i = 0; i < 8; i++) {
            const int mi = i * 32 + lane;           // float4 index into m
            const float4 k0 = sk4[mi];
            const float4 k1 = sk4[256 + mi];
            const float4 k2 = sk4[512 + mi];
            const float4 k3 = sk4[768 + mi];
            const float4 v0 = sv4[mi];
            const float4 v1 = sv4[256 + mi];
            const float4 v2 = sv4[512 + mi];
            const float4 v3 = sv4[768 + mi];

            #pragma unroll
            for (int j = 0; j < 4; j++) {
                const float4 bb = __ldg(&bp[j][mi]);
                // q pre-scaled by SCALE*log2e -> score*log2e = dot + bias*log2e
                float z0 = fmaf(qr[j].x, k0.x, fmaf(qr[j].y, k1.x, fmaf(qr[j].z, k2.x, qr[j].w * k3.x)));
                float z1 = fmaf(qr[j].x, k0.y, fmaf(qr[j].y, k1.y, fmaf(qr[j].z, k2.y, qr[j].w * k3.y)));
                float z2 = fmaf(qr[j].x, k0.z, fmaf(qr[j].y, k1.z, fmaf(qr[j].z, k2.z, qr[j].w * k3.z)));
                float z3 = fmaf(qr[j].x, k0.w, fmaf(qr[j].y, k1.w, fmaf(qr[j].z, k2.w, qr[j].w * k3.w)));
                const float e0 = ex2f(fmaf(bb.x, LOG2E, z0));
                const float e1 = ex2f(fmaf(bb.y, LOG2E, z1));
                const float e2 = ex2f(fmaf(bb.z, LOG2E, z2));
                const float e3 = ex2f(fmaf(bb.w, LOG2E, z3));
                sum[j] += (e0 + e1) + (e2 + e3);
                acc[j][0] = fmaf(e0, v0.x, fmaf(e1, v0.y, fmaf(e2, v0.z, fmaf(e3, v0.w, acc[j][0]))));
                acc[j][1] = fmaf(e0, v1.x, fmaf(e1, v1.y, fmaf(e2, v1.z, fmaf(e3, v1.w, acc[j][1]))));
                acc[j][2] = fmaf(e0, v2.x, fmaf(e1, v2.y, fmaf(e2, v2.z, fmaf(e3, v2.w, acc[j][2]))));
                acc[j][3] = fmaf(e0, v3.x, fmaf(e1, v3.y, fmaf(e2, v3.z, fmaf(e3, v3.w, acc[j][3]))));
            }
        }

        // warp reductions (all-lanes butterfly), lane 0 writes
        #pragma unroll
        for (int j = 0; j < 4; j++) {
            sum[j] = wred(sum[j]);
            #pragma unroll
            for (int d = 0; d < 4; d++) acc[j][d] = wred(acc[j][d]);
        }
        if (lane == 0) {
            float* ob = g_x2 + bh * 4 * NN;   // channel base = b*64 + h*4 = 4*bh
            #pragma unroll
            for (int j = 0; j < 4; j++) {
                const float inv = 1.0f / sum[j];
                #pragma unroll
                for (int d = 0; d < 4; d++)
                    ob[d * NN + row0 + j] = acc[j][d] * inv;
            }
        }
    }
}

// ---------------- kernel 3: output conv + BN(eval) + LeakyReLU ----------------
// grid (NN/16, BB), block 256.
// thread: nq = t&3 -> 4 n's (float4), og = t>>2 -> 4 channels {og, og+64, og+128, og+192}
__global__ void __launch_bounds__(256) out_kernel(
    const float* __restrict__ Wo, const float* __restrict__ bo,
    const float* __restrict__ gamma, const float* __restrict__ beta,
    const float* __restrict__ rmean, const float* __restrict__ rvar,
    float* __restrict__ out)
{
    const int b  = blockIdx.y;
    const int n0 = blockIdx.x * 16;
    const int t  = threadIdx.x;
    const int nq = t & 3;
    const int og = t >> 2;                // [0,64)
    const int n  = n0 + nq * 4;

    float acc[4][4];
    #pragma unroll
    for (int i = 0; i < 4; i++)
        #pragma unroll
        for (int jj = 0; jj < 4; jj++) acc[i][jj] = 0.f;

    const float4* xp = (const float4*)(g_x2 + b * 64 * NN + n);
    const float*  Wp = Wo + og * 64;      // rows og, og+64, og+128, og+192

    #pragma unroll 8
    for (int c = 0; c < 64; c++) {
        float4 xv = __ldg(xp + c * (NN / 4));
        #pragma unroll
        for (int i = 0; i < 4; i++) {
            float w = __ldg(Wp + i * 64 * 64 + c);
            acc[i][0] = fmaf(w, xv.x, acc[i][0]);
            acc[i][1] = fmaf(w, xv.y, acc[i][1]);
            acc[i][2] = fmaf(w, xv.z, acc[i][2]);
            acc[i][3] = fmaf(w, xv.w, acc[i][3]);
        }
    }

    #pragma unroll
    for (int i = 0; i < 4; i++) {
        const int o = og + i * 64;
        const float inv  = rsqrtf(__ldg(rvar + o) + 1e-5f);
        const float sc   = __ldg(gamma + o) * inv;
        const float sh   = __ldg(beta + o) - __ldg(rmean + o) * sc;
        const float bse  = fmaf(__ldg(bo + o), sc, sh);
        float4 r;
        r.x = fmaf(acc[i][0], sc, bse);
        r.y = fmaf(acc[i][1], sc, bse);
        r.z = fmaf(acc[i][2], sc, bse);
        r.w = fmaf(acc[i][3], sc, bse);
        r.x = r.x > 0.f ? r.x : 0.2f * r.x;
        r.y = r.y > 0.f ? r.y : 0.2f * r.y;
        r.z = r.z > 0.f ? r.z : 0.2f * r.z;
        r.w = r.w > 0.f ? r.w : 0.2f * r.w;
        *(float4*)(out + ((size_t)b * HID + o) * NN + n) = r;
    }
}

// ---------------- launch ----------------
extern "C" void kernel_launch(void* const* d_in, const int* in_sizes, int n_in,
                              void* d_out, int out_size)
{
    const float* q    = (const float*)d_in[0];
    const float* k    = (const float*)d_in[1];
    const float* v    = (const float*)d_in[2];
    const float* bias = (const float*)d_in[3];
    const float* Wq   = (const float*)d_in[4];
    const float* Wk   = (const float*)d_in[5];
    const float* Wv   = (const float*)d_in[6];
    const float* Wo   = (const float*)d_in[7];
    const float* bo   = (const float*)d_in[8];
    const float* gm   = (const float*)d_in[9];
    const float* bt   = (const float*)d_in[10];
    const float* rm   = (const float*)d_in[11];
    const float* rv   = (const float*)d_in[12];
    float* out = (float*)d_out;

    proj_kernel<<<dim3(NN / 32, BB, 3), 256>>>(q, k, v, Wq, Wk, Wv);
    attn_kernel<<<dim3(16, BB * HH), 256>>>(bias);
    out_kernel<<<dim3(NN / 16, BB), 256>>>(Wo, bo, gm, bt, rm, rv, out);
}

// round 5
// speedup vs baseline: 2.0361x; 1.7501x over previous
#include <cuda_runtime.h>

#define BB 4
#define HH 16
#define DD 4
#define HID 256
#define NN 1024
#define LOG2E 1.4426950408889634f
#define QPRE (0.5f * LOG2E)   /* SCALE * log2(e), folded into q at projection time */

// ---------------- device scratch (no allocation allowed) ----------------
__device__ float g_qh[BB*HH*NN*DD];   // [b][h][n][d], pre-scaled by QPRE
__device__ float g_kd[BB*HH*DD*NN];   // [b][h][d][n]
__device__ float g_vd[BB*HH*DD*NN];   // [b][h][d][n]
__device__ float g_x2[BB*HH*DD*NN];   // [b][h*4+d][n]  (post-transpose layout)

__device__ __forceinline__ float ex2f(float x){
    float y; asm("ex2.approx.ftz.f32 %0, %1;" : "=f"(y) : "f"(x)); return y;
}
__device__ __forceinline__ float wred(float v){
    v += __shfl_xor_sync(0xffffffffu, v, 16);
    v += __shfl_xor_sync(0xffffffffu, v, 8);
    v += __shfl_xor_sync(0xffffffffu, v, 4);
    v += __shfl_xor_sync(0xffffffffu, v, 2);
    v += __shfl_xor_sync(0xffffffffu, v, 1);
    return v;
}

// ---------------- kernel 1: projections + head scatter ----------------
// grid (NN/32, BB, 3), block 256
// thread: nq = t&7 -> 4 n's (float4), og = t>>3 -> 2 output channels
// c-loop batched by 8: 12 loads in flight per thread (MLP=12).
__global__ void __launch_bounds__(256, 3) proj_kernel(
    const float* __restrict__ q,
    const float* __restrict__ k,
    const float* __restrict__ v,
    const float* __restrict__ Wq,
    const float* __restrict__ Wk,
    const float* __restrict__ Wv)
{
    const int z  = blockIdx.z;
    const int b  = blockIdx.y;
    const int n0 = blockIdx.x * 32;

    const float* x = (z == 0) ? q : (z == 1) ? k : v;
    const float* W = (z == 0) ? Wq : (z == 1) ? Wk : Wv;

    const int t  = threadIdx.x;
    const int nq = t & 7;
    const int og = t >> 3;               // [0,32): 2 channels each
    const int n  = n0 + nq * 4;

    float acc[2][4];
    #pragma unroll
    for (int i = 0; i < 2; i++)
        #pragma unroll
        for (int jj = 0; jj < 4; jj++) acc[i][jj] = 0.f;

    const float4* xp  = (const float4*)(x + (size_t)b * HID * NN + n);
    const float*  w0p = W + og * 2 * HID;
    const float*  w1p = w0p + HID;

    #pragma unroll 1
    for (int c0 = 0; c0 < HID; c0 += 8) {
        float4 xv[8];
        #pragma unroll
        for (int u = 0; u < 8; u++)
            xv[u] = __ldg(xp + (size_t)(c0 + u) * (NN / 4));
        float4 wv0a = __ldg((const float4*)(w0p + c0));
        float4 wv0b = __ldg((const float4*)(w0p + c0 + 4));
        float4 wv1a = __ldg((const float4*)(w1p + c0));
        float4 wv1b = __ldg((const float4*)(w1p + c0 + 4));

        float w0s[8] = {wv0a.x, wv0a.y, wv0a.z, wv0a.w, wv0b.x, wv0b.y, wv0b.z, wv0b.w};
        float w1s[8] = {wv1a.x, wv1a.y, wv1a.z, wv1a.w, wv1b.x, wv1b.y, wv1b.z, wv1b.w};

        #pragma unroll
        for (int u = 0; u < 8; u++) {
            const float w0 = w0s[u], w1 = w1s[u];
            acc[0][0] = fmaf(w0, xv[u].x, acc[0][0]);
            acc[0][1] = fmaf(w0, xv[u].y, acc[0][1]);
            acc[0][2] = fmaf(w0, xv[u].z, acc[0][2]);
            acc[0][3] = fmaf(w0, xv[u].w, acc[0][3]);
            acc[1][0] = fmaf(w1, xv[u].x, acc[1][0]);
            acc[1][1] = fmaf(w1, xv[u].y, acc[1][1]);
            acc[1][2] = fmaf(w1, xv[u].z, acc[1][2]);
            acc[1][3] = fmaf(w1, xv[u].w, acc[1][3]);
        }
    }

    // scatter into head layouts. Mapping derived from reshape(B,D,N,H):
    //   channel o, position n  ->  d = o>>4, a = o&15, b2 = n>>4, h = n&15, n2 = a*64+b2
    #pragma unroll
    for (int i = 0; i < 2; i++) {
        const int o = og * 2 + i;
        const int d = o >> 4, a = o & 15;
        #pragma unroll
        for (int jj = 0; jj < 4; jj++) {
            const int np = n + jj;
            const int b2 = np >> 4, h = np & 15;
            const int n2 = a * 64 + b2;
            const float val = acc[i][jj];
            if (z == 0)      g_qh[(((b * HH + h) * NN + n2) << 2) + d] = val * QPRE;
            else if (z == 1) g_kd[((b * HH + h) * DD + d) * NN + n2] = val;
            else             g_vd[((b * HH + h) * DD + d) * NN + n2] = val;
        }
    }
}

// ---------------- kernel 2: fused attention ----------------
// grid (16, 64): x = 64-row chunk, y = bh. block 256 (8 warps).
// Each warp processes 4 rows simultaneously (amortizes K/V smem reads 4x).
__global__ void __launch_bounds__(256) attn_kernel(const float* __restrict__ bias)
{
    __shared__ float sK[DD * NN];
    __shared__ float sV[DD * NN];

    const int bh    = blockIdx.y;
    const int chunk = blockIdx.x;
    const int t     = threadIdx.x;

    // load K,V head tiles (4096 floats each) into smem
    {
        const float4* gk = (const float4*)(g_kd + bh * DD * NN);
        const float4* gv = (const float4*)(g_vd + bh * DD * NN);
        float4* sk4 = (float4*)sK;
        float4* sv4 = (float4*)sV;
        #pragma unroll
        for (int i = 0; i < 4; i++) {
            sk4[t + i * 256] = gk[t + i * 256];
            sv4[t + i * 256] = gv[t + i * 256];
        }
    }
    __syncthreads();

    const int warp = t >> 5, lane = t & 31;
    const float4* sk4 = (const float4*)sK;
    const float4* sv4 = (const float4*)sV;
    const float*  biasbh = bias + (size_t)bh * NN * NN;

    #pragma unroll 1
    for (int pass = 0; pass < 2; pass++) {
        const int row0 = chunk * 64 + warp * 8 + pass * 4;

        float4 qr[4];
        const float4* bp[4];
        #pragma unroll
        for (int j = 0; j < 4; j++) {
            qr[j] = *(const float4*)(g_qh + (bh * NN + row0 + j) * 4);
            bp[j] = (const float4*)(biasbh + (size_t)(row0 + j) * NN);
        }

        float sum[4] = {0.f, 0.f, 0.f, 0.f};
        float acc[4][4];
        #pragma unroll
        for (int j = 0; j < 4; j++)
            #pragma unroll
            for (int d = 0; d < 4; d++) acc[j][d] = 0.f;

        #pragma unroll
        for (int i = 0; i < 8; i++) {
            const int mi = i * 32 + lane;           // float4 index into m
            const float4 k0 = sk4[mi];
            const float4 k1 = sk4[256 + mi];
            const float4 k2 = sk4[512 + mi];
            const float4 k3 = sk4[768 + mi];
            const float4 v0 = sv4[mi];
            const float4 v1 = sv4[256 + mi];
            const float4 v2 = sv4[512 + mi];
            const float4 v3 = sv4[768 + mi];

            #pragma unroll
            for (int j = 0; j < 4; j++) {
                const float4 bb = __ldg(&bp[j][mi]);
                // q pre-scaled by SCALE*log2e -> score*log2e = dot + bias*log2e
                float z0 = fmaf(qr[j].x, k0.x, fmaf(qr[j].y, k1.x, fmaf(qr[j].z, k2.x, qr[j].w * k3.x)));
                float z1 = fmaf(qr[j].x, k0.y, fmaf(qr[j].y, k1.y, fmaf(qr[j].z, k2.y, qr[j].w * k3.y)));
                float z2 = fmaf(qr[j].x, k0.z, fmaf(qr[j].y, k1.z, fmaf(qr[j].z, k2.z, qr[j].w * k3.z)));
                float z3 = fmaf(qr[j].x, k0.w, fmaf(qr[j].y, k1.w, fmaf(qr[j].z, k2.w, qr[j].w * k3.w)));
                const float e0 = ex2f(fmaf(bb.x, LOG2E, z0));
                const float e1 = ex2f(fmaf(bb.y, LOG2E, z1));
                const float e2 = ex2f(fmaf(bb.z, LOG2E, z2));
                const float e3 = ex2f(fmaf(bb.w, LOG2E, z3));
                sum[j] += (e0 + e1) + (e2 + e3);
                acc[j][0] = fmaf(e0, v0.x, fmaf(e1, v0.y, fmaf(e2, v0.z, fmaf(e3, v0.w, acc[j][0]))));
                acc[j][1] = fmaf(e0, v1.x, fmaf(e1, v1.y, fmaf(e2, v1.z, fmaf(e3, v1.w, acc[j][1]))));
                acc[j][2] = fmaf(e0, v2.x, fmaf(e1, v2.y, fmaf(e2, v2.z, fmaf(e3, v2.w, acc[j][2]))));
                acc[j][3] = fmaf(e0, v3.x, fmaf(e1, v3.y, fmaf(e2, v3.z, fmaf(e3, v3.w, acc[j][3]))));
            }
        }

        // warp reductions (all-lanes butterfly), lane 0 writes
        #pragma unroll
        for (int j = 0; j < 4; j++) {
            sum[j] = wred(sum[j]);
            #pragma unroll
            for (int d = 0; d < 4; d++) acc[j][d] = wred(acc[j][d]);
        }
        if (lane == 0) {
            float* ob = g_x2 + bh * 4 * NN;   // channel base = b*64 + h*4 = 4*bh
            #pragma unroll
            for (int j = 0; j < 4; j++) {
                const float inv = 1.0f / sum[j];
                #pragma unroll
                for (int d = 0; d < 4; d++)
                    ob[d * NN + row0 + j] = acc[j][d] * inv;
            }
        }
    }
}

// ---------------- kernel 3: output conv + BN(eval) + LeakyReLU ----------------
// grid (NN/16, BB), block 256.
// thread: nq = t&3 -> 4 n's (float4), og = t>>2 -> 4 channels {og, og+64, og+128, og+192}
// c-loop batched by 4: 8 loads in flight (MLP=8).
__global__ void __launch_bounds__(256, 3) out_kernel(
    const float* __restrict__ Wo, const float* __restrict__ bo,
    const float* __restrict__ gamma, const float* __restrict__ beta,
    const float* __restrict__ rmean, const float* __restrict__ rvar,
    float* __restrict__ out)
{
    const int b  = blockIdx.y;
    const int n0 = blockIdx.x * 16;
    const int t  = threadIdx.x;
    const int nq = t & 3;
    const int og = t >> 2;                // [0,64)
    const int n  = n0 + nq * 4;

    float acc[4][4];
    #pragma unroll
    for (int i = 0; i < 4; i++)
        #pragma unroll
        for (int jj = 0; jj < 4; jj++) acc[i][jj] = 0.f;

    const float4* xp = (const float4*)(g_x2 + b * 64 * NN + n);
    const float*  Wp = Wo + og * 64;      // rows og, og+64, og+128, og+192

    #pragma unroll 1
    for (int c0 = 0; c0 < 64; c0 += 4) {
        float4 xv[4];
        #pragma unroll
        for (int u = 0; u < 4; u++)
            xv[u] = __ldg(xp + (c0 + u) * (NN / 4));
        float4 wv[4];
        #pragma unroll
        for (int i = 0; i < 4; i++)
            wv[i] = __ldg((const float4*)(Wp + i * 64 * 64 + c0));

        #pragma unroll
        for (int i = 0; i < 4; i++) {
            float ws[4] = {wv[i].x, wv[i].y, wv[i].z, wv[i].w};
            #pragma unroll
            for (int u = 0; u < 4; u++) {
                acc[i][0] = fmaf(ws[u], xv[u].x, acc[i][0]);
                acc[i][1] = fmaf(ws[u], xv[u].y, acc[i][1]);
                acc[i][2] = fmaf(ws[u], xv[u].z, acc[i][2]);
                acc[i][3] = fmaf(ws[u], xv[u].w, acc[i][3]);
            }
        }
    }

    #pragma unroll
    for (int i = 0; i < 4; i++) {
        const int o = og + i * 64;
        const float inv  = rsqrtf(__ldg(rvar + o) + 1e-5f);
        const float sc   = __ldg(gamma + o) * inv;
        const float sh   = __ldg(beta + o) - __ldg(rmean + o) * sc;
        const float bse  = fmaf(__ldg(bo + o), sc, sh);
        float4 r;
        r.x = fmaf(acc[i][0], sc, bse);
        r.y = fmaf(acc[i][1], sc, bse);
        r.z = fmaf(acc[i][2], sc, bse);
        r.w = fmaf(acc[i][3], sc, bse);
        r.x = r.x > 0.f ? r.x : 0.2f * r.x;
        r.y = r.y > 0.f ? r.y : 0.2f * r.y;
        r.z = r.z > 0.f ? r.z : 0.2f * r.z;
        r.w = r.w > 0.f ? r.w : 0.2f * r.w;
        *(float4*)(out + ((size_t)b * HID + o) * NN + n) = r;
    }
}

// ---------------- launch ----------------
extern "C" void kernel_launch(void* const* d_in, const int* in_sizes, int n_in,
                              void* d_out, int out_size)
{
    const float* q    = (const float*)d_in[0];
    const float* k    = (const float*)d_in[1];
    const float* v    = (const float*)d_in[2];
    const float* bias = (const float*)d_in[3];
    const float* Wq   = (const float*)d_in[4];
    const float* Wk   = (const float*)d_in[5];
    const float* Wv   = (const float*)d_in[6];
    const float* Wo   = (const float*)d_in[7];
    const float* bo   = (const float*)d_in[8];
    const float* gm   = (const float*)d_in[9];
    const float* bt   = (const float*)d_in[10];
    const float* rm   = (const float*)d_in[11];
    const float* rv   = (const float*)d_in[12];
    float* out = (float*)d_out;

    proj_kernel<<<dim3(NN / 32, BB, 3), 256>>>(q, k, v, Wq, Wk, Wv);
    attn_kernel<<<dim3(16, BB * HH), 256>>>(bias);
    out_kernel<<<dim3(NN / 16, BB), 256>>>(Wo, bo, gm, bt, rm, rv, out);
}

// round 6
// speedup vs baseline: 2.0372x; 1.0006x over previous
#include <cuda_runtime.h>
#include <cstdint>

#define BB 4
#define HH 16
#define DD 4
#define HID 256
#define NN 1024
#define LOG2E 1.4426950408889634f
#define QPRE (0.5f * LOG2E)   /* SCALE * log2(e), folded into q at projection time */

// ---------------- device scratch (no allocation allowed) ----------------
__device__ float g_qh[BB*HH*NN*DD];   // [b][h][n][d], pre-scaled by QPRE
__device__ float g_kd[BB*HH*DD*NN];   // [b][h][d][n]
__device__ float g_vd[BB*HH*DD*NN];   // [b][h][d][n]
__device__ float g_x2[BB*HH*DD*NN];   // [b][h*4+d][n]  (post-transpose layout)

__device__ __forceinline__ float ex2f(float x){
    float y; asm("ex2.approx.ftz.f32 %0, %1;" : "=f"(y) : "f"(x)); return y;
}
__device__ __forceinline__ float wred(float v){
    v += __shfl_xor_sync(0xffffffffu, v, 16);
    v += __shfl_xor_sync(0xffffffffu, v, 8);
    v += __shfl_xor_sync(0xffffffffu, v, 4);
    v += __shfl_xor_sync(0xffffffffu, v, 2);
    v += __shfl_xor_sync(0xffffffffu, v, 1);
    return v;
}

// ---- packed f32x2 helpers (PTX ISA 8.6+, sm_100+) ----
__device__ __forceinline__ uint64_t fma2(uint64_t a, uint64_t b, uint64_t c){
    uint64_t d; asm("fma.rn.f32x2 %0, %1, %2, %3;" : "=l"(d) : "l"(a), "l"(b), "l"(c)); return d;
}
__device__ __forceinline__ uint64_t mul2(uint64_t a, uint64_t b){
    uint64_t d; asm("mul.rn.f32x2 %0, %1, %2;" : "=l"(d) : "l"(a), "l"(b)); return d;
}
__device__ __forceinline__ uint64_t add2(uint64_t a, uint64_t b){
    uint64_t d; asm("add.rn.f32x2 %0, %1, %2;" : "=l"(d) : "l"(a), "l"(b)); return d;
}
__device__ __forceinline__ uint64_t pack2(float lo, float hi){
    uint64_t d; asm("mov.b64 %0, {%1, %2};" : "=l"(d) : "f"(lo), "f"(hi)); return d;
}
__device__ __forceinline__ void unpack2(uint64_t p, float& lo, float& hi){
    asm("mov.b64 {%0, %1}, %2;" : "=f"(lo), "=f"(hi) : "l"(p));
}

// ---------------- kernel 1: projections + head scatter ----------------
// grid (NN/32, BB, 3), block 256
// thread: nq = t&7 -> 4 n's (float4), og = t>>3 -> 2 output channels
// c-loop batched by 8, unroll 2 so ptxas overlaps next batch's loads with FMAs.
__global__ void __launch_bounds__(256, 2) proj_kernel(
    const float* __restrict__ q,
    const float* __restrict__ k,
    const float* __restrict__ v,
    const float* __restrict__ Wq,
    const float* __restrict__ Wk,
    const float* __restrict__ Wv)
{
    const int z  = blockIdx.z;
    const int b  = blockIdx.y;
    const int n0 = blockIdx.x * 32;

    const float* x = (z == 0) ? q : (z == 1) ? k : v;
    const float* W = (z == 0) ? Wq : (z == 1) ? Wk : Wv;

    const int t  = threadIdx.x;
    const int nq = t & 7;
    const int og = t >> 3;               // [0,32): 2 channels each
    const int n  = n0 + nq * 4;

    float acc[2][4];
    #pragma unroll
    for (int i = 0; i < 2; i++)
        #pragma unroll
        for (int jj = 0; jj < 4; jj++) acc[i][jj] = 0.f;

    const float4* xp  = (const float4*)(x + (size_t)b * HID * NN + n);
    const float*  w0p = W + og * 2 * HID;
    const float*  w1p = w0p + HID;

    #pragma unroll 2
    for (int c0 = 0; c0 < HID; c0 += 8) {
        float4 xv[8];
        #pragma unroll
        for (int u = 0; u < 8; u++)
            xv[u] = __ldg(xp + (size_t)(c0 + u) * (NN / 4));
        float4 wv0a = __ldg((const float4*)(w0p + c0));
        float4 wv0b = __ldg((const float4*)(w0p + c0 + 4));
        float4 wv1a = __ldg((const float4*)(w1p + c0));
        float4 wv1b = __ldg((const float4*)(w1p + c0 + 4));

        float w0s[8] = {wv0a.x, wv0a.y, wv0a.z, wv0a.w, wv0b.x, wv0b.y, wv0b.z, wv0b.w};
        float w1s[8] = {wv1a.x, wv1a.y, wv1a.z, wv1a.w, wv1b.x, wv1b.y, wv1b.z, wv1b.w};

        #pragma unroll
        for (int u = 0; u < 8; u++) {
            const float w0 = w0s[u], w1 = w1s[u];
            acc[0][0] = fmaf(w0, xv[u].x, acc[0][0]);
            acc[0][1] = fmaf(w0, xv[u].y, acc[0][1]);
            acc[0][2] = fmaf(w0, xv[u].z, acc[0][2]);
            acc[0][3] = fmaf(w0, xv[u].w, acc[0][3]);
            acc[1][0] = fmaf(w1, xv[u].x, acc[1][0]);
            acc[1][1] = fmaf(w1, xv[u].y, acc[1][1]);
            acc[1][2] = fmaf(w1, xv[u].z, acc[1][2]);
            acc[1][3] = fmaf(w1, xv[u].w, acc[1][3]);
        }
    }

    // scatter into head layouts. Mapping derived from reshape(B,D,N,H):
    //   channel o, position n  ->  d = o>>4, a = o&15, b2 = n>>4, h = n&15, n2 = a*64+b2
    #pragma unroll
    for (int i = 0; i < 2; i++) {
        const int o = og * 2 + i;
        const int d = o >> 4, a = o & 15;
        #pragma unroll
        for (int jj = 0; jj < 4; jj++) {
            const int np = n + jj;
            const int b2 = np >> 4, h = np & 15;
            const int n2 = a * 64 + b2;
            const float val = acc[i][jj];
            if (z == 0)      g_qh[(((b * HH + h) * NN + n2) << 2) + d] = val * QPRE;
            else if (z == 1) g_kd[((b * HH + h) * DD + d) * NN + n2] = val;
            else             g_vd[((b * HH + h) * DD + d) * NN + n2] = val;
        }
    }
}

// ---------------- kernel 2: fused attention (f32x2 packed) ----------------
// grid (32, 64): x = 32-row chunk, y = bh. block 128 (4 warps, 3 CTAs/SM).
// Each warp: 4 rows x 2 passes. Packed math over adjacent m.
__global__ void __launch_bounds__(128) attn_kernel(const float* __restrict__ bias)
{
    __shared__ __align__(16) float sK[DD * NN];
    __shared__ __align__(16) float sV[DD * NN];

    const int bh    = blockIdx.y;
    const int chunk = blockIdx.x;
    const int t     = threadIdx.x;

    // load K,V head tiles (4096 floats each = 1024 float4) into smem
    {
        const float4* gk = (const float4*)(g_kd + bh * DD * NN);
        const float4* gv = (const float4*)(g_vd + bh * DD * NN);
        float4* sk4 = (float4*)sK;
        float4* sv4 = (float4*)sV;
        #pragma unroll
        for (int i = 0; i < 8; i++) {
            sk4[t + i * 128] = gk[t + i * 128];
            sv4[t + i * 128] = gv[t + i * 128];
        }
    }
    __syncthreads();

    const int warp = t >> 5, lane = t & 31;
    const ulonglong2* sk2 = (const ulonglong2*)sK;   // [d*256 + mi] -> pairs (m0,m1),(m2,m3)
    const ulonglong2* sv2 = (const ulonglong2*)sV;
    const float*  biasbh = bias + (size_t)bh * NN * NN;
    const uint64_t L2E2 = pack2(LOG2E, LOG2E);

    #pragma unroll 1
    for (int pass = 0; pass < 2; pass++) {
        const int row0 = chunk * 32 + warp * 8 + pass * 4;

        uint64_t q2[4][4];                 // packed duplicated q components
        const ulonglong2* bp[4];
        #pragma unroll
        for (int j = 0; j < 4; j++) {
            float4 qr = *(const float4*)(g_qh + (bh * NN + row0 + j) * 4);
            q2[j][0] = pack2(qr.x, qr.x);
            q2[j][1] = pack2(qr.y, qr.y);
            q2[j][2] = pack2(qr.z, qr.z);
            q2[j][3] = pack2(qr.w, qr.w);
            bp[j] = (const ulonglong2*)(biasbh + (size_t)(row0 + j) * NN);
        }

        uint64_t sum2[4];
        uint64_t acc2[4][4];
        #pragma unroll
        for (int j = 0; j < 4; j++) {
            sum2[j] = 0ull;
            #pragma unroll
            for (int d = 0; d < 4; d++) acc2[j][d] = 0ull;
        }

        #pragma unroll
        for (int i = 0; i < 8; i++) {
            const int mi = i * 32 + lane;           // float4 index into m
            const ulonglong2 k0 = sk2[mi];
            const ulonglong2 k1 = sk2[256 + mi];
            const ulonglong2 k2 = sk2[512 + mi];
            const ulonglong2 k3 = sk2[768 + mi];
            const ulonglong2 v0 = sv2[mi];
            const ulonglong2 v1 = sv2[256 + mi];
            const ulonglong2 v2 = sv2[512 + mi];
            const ulonglong2 v3 = sv2[768 + mi];

            #pragma unroll
            for (int j = 0; j < 4; j++) {
                const ulonglong2 bb = __ldg(&bp[j][mi]);
                // scores for m-pair (0,1) and (2,3): z = q.k (q pre-scaled), then + bias*log2e
                uint64_t z01 = mul2(q2[j][0], k0.x);
                uint64_t z23 = mul2(q2[j][0], k0.y);
                z01 = fma2(q2[j][1], k1.x, z01);
                z23 = fma2(q2[j][1], k1.y, z23);
                z01 = fma2(q2[j][2], k2.x, z01);
                z23 = fma2(q2[j][2], k2.y, z23);
                z01 = fma2(q2[j][3], k3.x, z01);
                z23 = fma2(q2[j][3], k3.y, z23);
                z01 = fma2(bb.x, L2E2, z01);
                z23 = fma2(bb.y, L2E2, z23);
                float f0, f1, f2, f3;
                unpack2(z01, f0, f1);
                unpack2(z23, f2, f3);
                const uint64_t e01 = pack2(ex2f(f0), ex2f(f1));
                const uint64_t e23 = pack2(ex2f(f2), ex2f(f3));
                sum2[j] = add2(sum2[j], add2(e01, e23));
                acc2[j][0] = fma2(e01, v0.x, acc2[j][0]);
                acc2[j][0] = fma2(e23, v0.y, acc2[j][0]);
                acc2[j][1] = fma2(e01, v1.x, acc2[j][1]);
                acc2[j][1] = fma2(e23, v1.y, acc2[j][1]);
                acc2[j][2] = fma2(e01, v2.x, acc2[j][2]);
                acc2[j][2] = fma2(e23, v2.y, acc2[j][2]);
                acc2[j][3] = fma2(e01, v3.x, acc2[j][3]);
                acc2[j][3] = fma2(e23, v3.y, acc2[j][3]);
            }
        }

        // collapse pairs, warp-reduce, lane 0 writes
        #pragma unroll
        for (int j = 0; j < 4; j++) {
            float slo, shi;
            unpack2(sum2[j], slo, shi);
            float sum = wred(slo + shi);
            float acc[4];
            #pragma unroll
            for (int d = 0; d < 4; d++) {
                float alo, ahi;
                unpack2(acc2[j][d], alo, ahi);
                acc[d] = wred(alo + ahi);
            }
            if (lane == 0) {
                float* ob = g_x2 + bh * 4 * NN;   // channel base = 4*bh
                const float inv = 1.0f / sum;
                #pragma unroll
                for (int d = 0; d < 4; d++)
                    ob[d * NN + row0 + j] = acc[d] * inv;
            }
        }
    }
}

// ---------------- kernel 3: output conv + BN(eval) + LeakyReLU ----------------
// grid (NN/16, BB), block 256.
// thread: nq = t&3 -> 4 n's (float4), og = t>>2 -> 4 channels {og, og+64, og+128, og+192}
__global__ void __launch_bounds__(256, 3) out_kernel(
    const float* __restrict__ Wo, const float* __restrict__ bo,
    const float* __restrict__ gamma, const float* __restrict__ beta,
    const float* __restrict__ rmean, const float* __restrict__ rvar,
    float* __restrict__ out)
{
    const int b  = blockIdx.y;
    const int n0 = blockIdx.x * 16;
    const int t  = threadIdx.x;
    const int nq = t & 3;
    const int og = t >> 2;                // [0,64)
    const int n  = n0 + nq * 4;

    float acc[4][4];
    #pragma unroll
    for (int i = 0; i < 4; i++)
        #pragma unroll
        for (int jj = 0; jj < 4; jj++) acc[i][jj] = 0.f;

    const float4* xp = (const float4*)(g_x2 + b * 64 * NN + n);
    const float*  Wp = Wo + og * 64;      // rows og, og+64, og+128, og+192

    #pragma unroll 2
    for (int c0 = 0; c0 < 64; c0 += 4) {
        float4 xv[4];
        #pragma unroll
        for (int u = 0; u < 4; u++)
            xv[u] = __ldg(xp + (c0 + u) * (NN / 4));
        float4 wv[4];
        #pragma unroll
        for (int i = 0; i < 4; i++)
            wv[i] = __ldg((const float4*)(Wp + i * 64 * 64 + c0));

        #pragma unroll
        for (int i = 0; i < 4; i++) {
            float ws[4] = {wv[i].x, wv[i].y, wv[i].z, wv[i].w};
            #pragma unroll
            for (int u = 0; u < 4; u++) {
                acc[i][0] = fmaf(ws[u], xv[u].x, acc[i][0]);
                acc[i][1] = fmaf(ws[u], xv[u].y, acc[i][1]);
                acc[i][2] = fmaf(ws[u], xv[u].z, acc[i][2]);
                acc[i][3] = fmaf(ws[u], xv[u].w, acc[i][3]);
            }
        }
    }

    #pragma unroll
    for (int i = 0; i < 4; i++) {
        const int o = og + i * 64;
        const float inv  = rsqrtf(__ldg(rvar + o) + 1e-5f);
        const float sc   = __ldg(gamma + o) * inv;
        const float sh   = __ldg(beta + o) - __ldg(rmean + o) * sc;
        const float bse  = fmaf(__ldg(bo + o), sc, sh);
        float4 r;
        r.x = fmaf(acc[i][0], sc, bse);
        r.y = fmaf(acc[i][1], sc, bse);
        r.z = fmaf(acc[i][2], sc, bse);
        r.w = fmaf(acc[i][3], sc, bse);
        r.x = r.x > 0.f ? r.x : 0.2f * r.x;
        r.y = r.y > 0.f ? r.y : 0.2f * r.y;
        r.z = r.z > 0.f ? r.z : 0.2f * r.z;
        r.w = r.w > 0.f ? r.w : 0.2f * r.w;
        *(float4*)(out + ((size_t)b * HID + o) * NN + n) = r;
    }
}

// ---------------- launch ----------------
extern "C" void kernel_launch(void* const* d_in, const int* in_sizes, int n_in,
                              void* d_out, int out_size)
{
    const float* q    = (const float*)d_in[0];
    const float* k    = (const float*)d_in[1];
    const float* v    = (const float*)d_in[2];
    const float* bias = (const float*)d_in[3];
    const float* Wq   = (const float*)d_in[4];
    const float* Wk   = (const float*)d_in[5];
    const float* Wv   = (const float*)d_in[6];
    const float* Wo   = (const float*)d_in[7];
    const float* bo   = (const float*)d_in[8];
    const float* gm   = (const float*)d_in[9];
    const float* bt   = (const float*)d_in[10];
    const float* rm   = (const float*)d_in[11];
    const float* rv   = (const float*)d_in[12];
    float* out = (float*)d_out;

    proj_kernel<<<dim3(NN / 32, BB, 3), 256>>>(q, k, v, Wq, Wk, Wv);
    attn_kernel<<<dim3(32, BB * HH), 128>>>(bias);
    out_kernel<<<dim3(NN / 16, BB), 256>>>(Wo, bo, gm, bt, rm, rv, out);
}